// round 2
// baseline (speedup 1.0000x reference)
#include <cuda_runtime.h>
#include <math.h>

#define Bsz 2
#define Tt  2048
#define Cc  2048
#define NH  8
#define HD  256
#define HH  128
#define SCALE 0.08838834764831845f   // 1/sqrt(128)

// ---------------- scratch (device globals: sanctioned, no alloc) ----------------
__device__ float g_Q [Bsz*Tt*Cc];
__device__ float g_K [Bsz*Tt*Cc];
__device__ float g_V [Bsz*Tt*Cc];
__device__ float g_q1[Bsz*NH*Tt*HH];
__device__ float g_q2[Bsz*NH*Tt*HH];
__device__ float g_k1[Bsz*NH*Tt*HH];
__device__ float g_k2[Bsz*NH*Tt*HH];
__device__ float g_vt[Bsz*NH*Tt*HD];
__device__ float g_y [Bsz*Tt*Cc];
__device__ float g_lam;

// ---------------- SGEMM: C[M,N] = alpha * A[M,K] @ B[N,K]^T (NT, row-major) ----
__global__ __launch_bounds__(256)
void sgemm_nt(const float* __restrict__ A, const float* __restrict__ B,
              float* __restrict__ C, int M, int N, int K, float alpha)
{
    __shared__ float As[16][128];
    __shared__ float Bs[16][128];
    const int tid = threadIdx.x;
    const int m0 = blockIdx.y * 128;
    const int n0 = blockIdx.x * 128;
    const int tx = tid & 15;
    const int ty = tid >> 4;
    const int lr = tid >> 2;         // 0..63
    const int lc = (tid & 3) << 2;   // 0,4,8,12
    const float* Ap = A + (size_t)(m0 + lr) * K + lc;
    const float* Bp = B + (size_t)(n0 + lr) * K + lc;

    float acc[8][8];
#pragma unroll
    for (int i = 0; i < 8; i++)
#pragma unroll
        for (int j = 0; j < 8; j++) acc[i][j] = 0.f;

    for (int k0 = 0; k0 < K; k0 += 16) {
        float4 a0 = *(const float4*)(Ap + k0);
        float4 a1 = *(const float4*)(Ap + (size_t)64 * K + k0);
        float4 b0 = *(const float4*)(Bp + k0);
        float4 b1 = *(const float4*)(Bp + (size_t)64 * K + k0);
        __syncthreads();
        As[lc+0][lr]    = a0.x; As[lc+1][lr]    = a0.y; As[lc+2][lr]    = a0.z; As[lc+3][lr]    = a0.w;
        As[lc+0][lr+64] = a1.x; As[lc+1][lr+64] = a1.y; As[lc+2][lr+64] = a1.z; As[lc+3][lr+64] = a1.w;
        Bs[lc+0][lr]    = b0.x; Bs[lc+1][lr]    = b0.y; Bs[lc+2][lr]    = b0.z; Bs[lc+3][lr]    = b0.w;
        Bs[lc+0][lr+64] = b1.x; Bs[lc+1][lr+64] = b1.y; Bs[lc+2][lr+64] = b1.z; Bs[lc+3][lr+64] = b1.w;
        __syncthreads();
#pragma unroll
        for (int kk = 0; kk < 16; kk++) {
            float a[8], b[8];
            *(float4*)(a)     = *(const float4*)&As[kk][ty*8];
            *(float4*)(a + 4) = *(const float4*)&As[kk][ty*8 + 4];
            *(float4*)(b)     = *(const float4*)&Bs[kk][tx*8];
            *(float4*)(b + 4) = *(const float4*)&Bs[kk][tx*8 + 4];
#pragma unroll
            for (int i = 0; i < 8; i++)
#pragma unroll
                for (int j = 0; j < 8; j++)
                    acc[i][j] = fmaf(a[i], b[j], acc[i][j]);
        }
    }
#pragma unroll
    for (int i = 0; i < 8; i++) {
        float* Cp = C + (size_t)(m0 + ty*8 + i) * N + n0 + tx*8;
        float4 c0 = make_float4(alpha*acc[i][0], alpha*acc[i][1], alpha*acc[i][2], alpha*acc[i][3]);
        float4 c1 = make_float4(alpha*acc[i][4], alpha*acc[i][5], alpha*acc[i][6], alpha*acc[i][7]);
        *(float4*)Cp       = c0;
        *(float4*)(Cp + 4) = c1;
    }
}

// ---------------- lambda scalar ----------------
__global__ void lam_kernel(const float* __restrict__ lq1, const float* __restrict__ lk1,
                           const float* __restrict__ lq2, const float* __restrict__ lk2)
{
    int d = threadIdx.x;             // 256 threads
    float p1 = lq1[d] * lk1[d];
    float p2 = lq2[d] * lk2[d];
#pragma unroll
    for (int o = 16; o; o >>= 1) {
        p1 += __shfl_xor_sync(0xffffffffu, p1, o);
        p2 += __shfl_xor_sync(0xffffffffu, p2, o);
    }
    __shared__ float w1[8], w2[8];
    if ((d & 31) == 0) { w1[d >> 5] = p1; w2[d >> 5] = p2; }
    __syncthreads();
    if (d == 0) {
        float s1 = 0.f, s2 = 0.f;
        for (int i = 0; i < 8; i++) { s1 += w1[i]; s2 += w2[i]; }
        g_lam = expf(s1) - expf(s2) + 0.2f;
    }
}

// ---------------- rmsnorm + (head-indexed) rotary + transpose ----------------
__device__ __forceinline__ void rot_one(const float* __restrict__ src, float* __restrict__ dst,
                                        float* sv, float* ws, float* srn, int d, float cj, float sj)
{
    float v = src[d];
    sv[d] = v;
    float sq = v * v;
#pragma unroll
    for (int o = 16; o; o >>= 1) sq += __shfl_xor_sync(0xffffffffu, sq, o);
    if ((d & 31) == 0) ws[d >> 5] = sq;
    __syncthreads();
    if (d == 0) *srn = rsqrtf((ws[0] + ws[1] + ws[2] + ws[3]) * (1.0f / 128.0f) + 1.1920929e-07f);
    __syncthreads();
    float rn = *srn;
    float vd = sv[d] * rn;
    float vp = sv[(d < 64) ? d + 64 : d - 64] * rn;
    dst[d] = (d < 64) ? (vd * cj + vp * sj) : (vd * cj - vp * sj);
    __syncthreads();
}

__global__ __launch_bounds__(128)
void prep_kernel()
{
    int idx = blockIdx.x;            // (b*T + t)*NH + h
    int h = idx & 7;
    int t = (idx >> 3) & 2047;
    int b = idx >> 14;
    int d = threadIdx.x;
    __shared__ float sv[128];
    __shared__ float ws[4];
    __shared__ float srn;

    int j = (d < 64) ? d : d - 64;
    // buggy-rotary angle: position index = head index h
    float ang = (float)h * powf(10000.0f, -(float)j * (1.0f / 64.0f));
    float cj = cosf(ang), sj = sinf(ang);

    size_t inb  = ((size_t)(b * Tt) + t) * Cc + h * HD;
    size_t outb = ((size_t)(b * NH + h) * Tt + t) * HH;

    rot_one(g_Q + inb,      g_q1 + outb, sv, ws, &srn, d, cj, sj);
    rot_one(g_Q + inb + HH, g_q2 + outb, sv, ws, &srn, d, cj, sj);
    rot_one(g_K + inb,      g_k1 + outb, sv, ws, &srn, d, cj, sj);
    rot_one(g_K + inb + HH, g_k2 + outb, sv, ws, &srn, d, cj, sj);

    const float* vsrc = g_V + inb;
    float* vdst = g_vt + ((size_t)(b * NH + h) * Tt + t) * HD;
    vdst[d]       = vsrc[d];
    vdst[d + 128] = vsrc[d + 128];
}

// ---------------- dual causal flash attention (fp32) ----------------
// grid: (T/16, B*NH), block 512 = 16 warps, 1 query per warp, 32-key tiles.
__global__ __launch_bounds__(512)
void attn_kernel()
{
    extern __shared__ float sm[];
    float (*k1s)[129] = (float(*)[129])(sm);
    float (*k2s)[129] = (float(*)[129])(sm + 32 * 129);
    float (*vsm)[256] = (float(*)[256])(sm + 2 * 32 * 129);
    float (*q1s)[128] = (float(*)[128])(sm + 2 * 32 * 129 + 32 * 256);
    float (*q2s)[128] = (float(*)[128])(sm + 2 * 32 * 129 + 32 * 256 + 16 * 128);

    const int tid  = threadIdx.x;
    const int lane = tid & 31;
    const int w    = tid >> 5;
    const int bh   = blockIdx.y;
    const int t    = blockIdx.x * 16 + w;

    const float* q1p = g_q1 + ((size_t)bh * Tt + t) * HH;
    const float* q2p = g_q2 + ((size_t)bh * Tt + t) * HH;
    ((float4*)q1s[w])[lane] = ((const float4*)q1p)[lane];
    ((float4*)q2s[w])[lane] = ((const float4*)q2p)[lane];
    __syncwarp();

    float m1 = -1e30f, m2 = -1e30f, l1 = 0.f, l2 = 0.f;
    float acc1[8], acc2[8];
#pragma unroll
    for (int i = 0; i < 8; i++) { acc1[i] = 0.f; acc2[i] = 0.f; }

    const int ntiles = (blockIdx.x * 16 + 15) / 32 + 1;
    const float* k1b = g_k1 + (size_t)bh * Tt * HH;
    const float* k2b = g_k2 + (size_t)bh * Tt * HH;
    const float* vb  = g_vt + (size_t)bh * Tt * HD;

    const int row = tid >> 4;        // 0..31
    const int cg  = tid & 15;

    for (int kb = 0; kb < ntiles; kb++) {
        __syncthreads();
        {
            const float* s1 = k1b + (size_t)(kb * 32 + row) * HH + cg * 8;
            float4 x0 = ((const float4*)s1)[0];
            float4 x1 = ((const float4*)s1)[1];
            float* dp = &k1s[row][cg * 8];
            dp[0]=x0.x; dp[1]=x0.y; dp[2]=x0.z; dp[3]=x0.w;
            dp[4]=x1.x; dp[5]=x1.y; dp[6]=x1.z; dp[7]=x1.w;

            const float* s2 = k2b + (size_t)(kb * 32 + row) * HH + cg * 8;
            float4 y0 = ((const float4*)s2)[0];
            float4 y1 = ((const float4*)s2)[1];
            float* dq = &k2s[row][cg * 8];
            dq[0]=y0.x; dq[1]=y0.y; dq[2]=y0.z; dq[3]=y0.w;
            dq[4]=y1.x; dq[5]=y1.y; dq[6]=y1.z; dq[7]=y1.w;

            const float* sv = vb + (size_t)(kb * 32 + row) * HD + cg * 16;
            float4* dv = (float4*)&vsm[row][cg * 16];
            dv[0] = ((const float4*)sv)[0];
            dv[1] = ((const float4*)sv)[1];
            dv[2] = ((const float4*)sv)[2];
            dv[3] = ((const float4*)sv)[3];
        }
        __syncthreads();

        int krem = t - kb * 32 + 1;
        if (krem > 0) {
            int nk = krem < 32 ? krem : 32;
            float s1 = 0.f, s2 = 0.f;
            const float* kr1 = k1s[lane];
            const float* kr2 = k2s[lane];
            const float* qa  = q1s[w];
            const float* qb  = q2s[w];
#pragma unroll 16
            for (int d = 0; d < HH; d++) {
                s1 = fmaf(qa[d], kr1[d], s1);
                s2 = fmaf(qb[d], kr2[d], s2);
            }
            s1 *= SCALE; s2 *= SCALE;
            if (lane >= nk) { s1 = -1e30f; s2 = -1e30f; }

            float mx1 = s1, mx2 = s2;
#pragma unroll
            for (int o = 16; o; o >>= 1) {
                mx1 = fmaxf(mx1, __shfl_xor_sync(0xffffffffu, mx1, o));
                mx2 = fmaxf(mx2, __shfl_xor_sync(0xffffffffu, mx2, o));
            }
            float nm1 = fmaxf(m1, mx1), nm2 = fmaxf(m2, mx2);
            float p1 = __expf(s1 - nm1), p2 = __expf(s2 - nm2);
            float c1 = __expf(m1 - nm1), c2 = __expf(m2 - nm2);
            float sp1 = p1, sp2 = p2;
#pragma unroll
            for (int o = 16; o; o >>= 1) {
                sp1 += __shfl_xor_sync(0xffffffffu, sp1, o);
                sp2 += __shfl_xor_sync(0xffffffffu, sp2, o);
            }
            l1 = l1 * c1 + sp1; l2 = l2 * c2 + sp2;
            m1 = nm1; m2 = nm2;
#pragma unroll
            for (int i = 0; i < 8; i++) { acc1[i] *= c1; acc2[i] *= c2; }

#pragma unroll 4
            for (int jj = 0; jj < 32; jj++) {
                float pj1 = __shfl_sync(0xffffffffu, p1, jj);
                float pj2 = __shfl_sync(0xffffffffu, p2, jj);
                const float* vr = vsm[jj];
#pragma unroll
                for (int i = 0; i < 8; i++) {
                    float vv = vr[lane + 32 * i];
                    acc1[i] = fmaf(pj1, vv, acc1[i]);
                    acc2[i] = fmaf(pj2, vv, acc2[i]);
                }
            }
        }
    }

    float lam = g_lam;
    float r1 = 1.f / l1, r2 = lam / l2;
    int b = bh >> 3, h = bh & 7;
    float* yp = g_y + ((size_t)(b * Tt) + t) * Cc + h * HD;
#pragma unroll
    for (int i = 0; i < 8; i++)
        yp[lane + 32 * i] = acc1[i] * r1 - acc2[i] * r2;
}

// ---------------- launcher ----------------
extern "C" void kernel_launch(void* const* d_in, const int* in_sizes, int n_in,
                              void* d_out, int out_size)
{
    const float* x   = (const float*)d_in[0];
    const float* wq  = (const float*)d_in[1];
    const float* wk  = (const float*)d_in[2];
    const float* wv  = (const float*)d_in[3];
    const float* wo  = (const float*)d_in[4];
    const float* lq1 = (const float*)d_in[5];
    const float* lk1 = (const float*)d_in[6];
    const float* lq2 = (const float*)d_in[7];
    const float* lk2 = (const float*)d_in[8];
    float* out = (float*)d_out;

    void *pQ, *pK, *pV, *pY;
    cudaGetSymbolAddress(&pQ, g_Q);
    cudaGetSymbolAddress(&pK, g_K);
    cudaGetSymbolAddress(&pV, g_V);
    cudaGetSymbolAddress(&pY, g_y);

    dim3 gg(Cc / 128, (Bsz * Tt) / 128);
    sgemm_nt<<<gg, 256>>>(x, wq, (float*)pQ, Bsz * Tt, Cc, Cc, 1.0f);
    sgemm_nt<<<gg, 256>>>(x, wk, (float*)pK, Bsz * Tt, Cc, Cc, 1.0f);
    sgemm_nt<<<gg, 256>>>(x, wv, (float*)pV, Bsz * Tt, Cc, Cc, 1.0f);
    lam_kernel<<<1, 256>>>(lq1, lk1, lq2, lk2);
    prep_kernel<<<Bsz * Tt * NH, 128>>>();

    int smem = (2 * 32 * 129 + 32 * 256 + 2 * 16 * 128) * 4;  // 82176 B
    cudaFuncSetAttribute(attn_kernel, cudaFuncAttributeMaxDynamicSharedMemorySize, smem);
    attn_kernel<<<dim3(Tt / 16, Bsz * NH), 512, smem>>>();

    sgemm_nt<<<gg, 256>>>((const float*)pY, wo, out, Bsz * Tt, Cc, Cc, 0.8f);
}

// round 3
// speedup vs baseline: 1.0072x; 1.0072x over previous
#include <cuda_runtime.h>
#include <math.h>

#define Bsz 2
#define Tt  2048
#define Cc  2048
#define NH  8
#define HD  256
#define HH  128
#define SCALE 0.08838834764831845f   // 1/sqrt(128)

// ---------------- scratch (device globals: sanctioned, no alloc) ----------------
__device__ float g_Q [Bsz*Tt*Cc];
__device__ float g_K [Bsz*Tt*Cc];
__device__ float g_V [Bsz*Tt*Cc];
__device__ float g_q1[Bsz*NH*Tt*HH];
__device__ float g_q2[Bsz*NH*Tt*HH];
__device__ float g_k1[Bsz*NH*Tt*HH];
__device__ float g_k2[Bsz*NH*Tt*HH];
__device__ float g_vt[Bsz*NH*Tt*HD];
__device__ float g_y [Bsz*Tt*Cc];
__device__ float g_lam;

// ---------------- SGEMM: C[M,N] = alpha * A[M,K] @ B[N,K]^T (NT, row-major) ----
__global__ __launch_bounds__(256)
void sgemm_nt(const float* __restrict__ A, const float* __restrict__ B,
              float* __restrict__ C, int M, int N, int K, float alpha)
{
    __shared__ float As[16][128];
    __shared__ float Bs[16][128];
    const int tid = threadIdx.x;
    const int m0 = blockIdx.y * 128;
    const int n0 = blockIdx.x * 128;
    const int tx = tid & 15;
    const int ty = tid >> 4;
    const int lr = tid >> 2;         // 0..63
    const int lc = (tid & 3) << 2;   // 0,4,8,12
    const float* Ap = A + (size_t)(m0 + lr) * K + lc;
    const float* Bp = B + (size_t)(n0 + lr) * K + lc;

    float acc[8][8];
#pragma unroll
    for (int i = 0; i < 8; i++)
#pragma unroll
        for (int j = 0; j < 8; j++) acc[i][j] = 0.f;

    for (int k0 = 0; k0 < K; k0 += 16) {
        float4 a0 = *(const float4*)(Ap + k0);
        float4 a1 = *(const float4*)(Ap + (size_t)64 * K + k0);
        float4 b0 = *(const float4*)(Bp + k0);
        float4 b1 = *(const float4*)(Bp + (size_t)64 * K + k0);
        __syncthreads();
        As[lc+0][lr]    = a0.x; As[lc+1][lr]    = a0.y; As[lc+2][lr]    = a0.z; As[lc+3][lr]    = a0.w;
        As[lc+0][lr+64] = a1.x; As[lc+1][lr+64] = a1.y; As[lc+2][lr+64] = a1.z; As[lc+3][lr+64] = a1.w;
        Bs[lc+0][lr]    = b0.x; Bs[lc+1][lr]    = b0.y; Bs[lc+2][lr]    = b0.z; Bs[lc+3][lr]    = b0.w;
        Bs[lc+0][lr+64] = b1.x; Bs[lc+1][lr+64] = b1.y; Bs[lc+2][lr+64] = b1.z; Bs[lc+3][lr+64] = b1.w;
        __syncthreads();
#pragma unroll
        for (int kk = 0; kk < 16; kk++) {
            float a[8], b[8];
            *(float4*)(a)     = *(const float4*)&As[kk][ty*8];
            *(float4*)(a + 4) = *(const float4*)&As[kk][ty*8 + 4];
            *(float4*)(b)     = *(const float4*)&Bs[kk][tx*8];
            *(float4*)(b + 4) = *(const float4*)&Bs[kk][tx*8 + 4];
#pragma unroll
            for (int i = 0; i < 8; i++)
#pragma unroll
                for (int j = 0; j < 8; j++)
                    acc[i][j] = fmaf(a[i], b[j], acc[i][j]);
        }
    }
#pragma unroll
    for (int i = 0; i < 8; i++) {
        float* Cp = C + (size_t)(m0 + ty*8 + i) * N + n0 + tx*8;
        float4 c0 = make_float4(alpha*acc[i][0], alpha*acc[i][1], alpha*acc[i][2], alpha*acc[i][3]);
        float4 c1 = make_float4(alpha*acc[i][4], alpha*acc[i][5], alpha*acc[i][6], alpha*acc[i][7]);
        *(float4*)Cp       = c0;
        *(float4*)(Cp + 4) = c1;
    }
}

// ---------------- lambda scalar ----------------
__global__ void lam_kernel(const float* __restrict__ lq1, const float* __restrict__ lk1,
                           const float* __restrict__ lq2, const float* __restrict__ lk2)
{
    int d = threadIdx.x;             // 256 threads
    float p1 = lq1[d] * lk1[d];
    float p2 = lq2[d] * lk2[d];
#pragma unroll
    for (int o = 16; o; o >>= 1) {
        p1 += __shfl_xor_sync(0xffffffffu, p1, o);
        p2 += __shfl_xor_sync(0xffffffffu, p2, o);
    }
    __shared__ float w1[8], w2[8];
    if ((d & 31) == 0) { w1[d >> 5] = p1; w2[d >> 5] = p2; }
    __syncthreads();
    if (d == 0) {
        float s1 = 0.f, s2 = 0.f;
        for (int i = 0; i < 8; i++) { s1 += w1[i]; s2 += w2[i]; }
        g_lam = expf(s1) - expf(s2) + 0.2f;
    }
}

// ---------------- rmsnorm + (head-indexed) rotary + transpose ----------------
__device__ __forceinline__ void rot_one(const float* __restrict__ src, float* __restrict__ dst,
                                        float* sv, float* ws, float* srn, int d, float cj, float sj)
{
    float v = src[d];
    sv[d] = v;
    float sq = v * v;
#pragma unroll
    for (int o = 16; o; o >>= 1) sq += __shfl_xor_sync(0xffffffffu, sq, o);
    if ((d & 31) == 0) ws[d >> 5] = sq;
    __syncthreads();
    if (d == 0) *srn = rsqrtf((ws[0] + ws[1] + ws[2] + ws[3]) * (1.0f / 128.0f) + 1.1920929e-07f);
    __syncthreads();
    float rn = *srn;
    float vd = sv[d] * rn;
    float vp = sv[(d < 64) ? d + 64 : d - 64] * rn;
    dst[d] = (d < 64) ? (vd * cj + vp * sj) : (vd * cj - vp * sj);
    __syncthreads();
}

__global__ __launch_bounds__(128)
void prep_kernel()
{
    int idx = blockIdx.x;            // (b*T + t)*NH + h
    int h = idx & 7;
    int t = (idx >> 3) & 2047;
    int b = idx >> 14;
    int d = threadIdx.x;
    __shared__ float sv[128];
    __shared__ float ws[4];
    __shared__ float srn;

    int j = (d < 64) ? d : d - 64;
    // buggy-rotary angle: position index = head index h
    float ang = (float)h * powf(10000.0f, -(float)j * (1.0f / 64.0f));
    float cj = cosf(ang), sj = sinf(ang);

    size_t inb  = ((size_t)(b * Tt) + t) * Cc + h * HD;
    size_t outb = ((size_t)(b * NH + h) * Tt + t) * HH;

    rot_one(g_Q + inb,      g_q1 + outb, sv, ws, &srn, d, cj, sj);
    rot_one(g_Q + inb + HH, g_q2 + outb, sv, ws, &srn, d, cj, sj);
    rot_one(g_K + inb,      g_k1 + outb, sv, ws, &srn, d, cj, sj);
    rot_one(g_K + inb + HH, g_k2 + outb, sv, ws, &srn, d, cj, sj);

    const float* vsrc = g_V + inb;
    float* vdst = g_vt + ((size_t)(b * NH + h) * Tt + t) * HD;
    vdst[d]       = vsrc[d];
    vdst[d + 128] = vsrc[d + 128];
}

// ---------------- dual causal flash attention (fp32) ----------------
// grid: (T/16, B*NH), block 512 = 16 warps, 1 query per warp, 32-key tiles.
__global__ __launch_bounds__(512)
void attn_kernel()
{
    extern __shared__ float sm[];
    float (*k1s)[129] = (float(*)[129])(sm);
    float (*k2s)[129] = (float(*)[129])(sm + 32 * 129);
    float (*vsm)[256] = (float(*)[256])(sm + 2 * 32 * 129);
    float (*q1s)[128] = (float(*)[128])(sm + 2 * 32 * 129 + 32 * 256);
    float (*q2s)[128] = (float(*)[128])(sm + 2 * 32 * 129 + 32 * 256 + 16 * 128);

    const int tid  = threadIdx.x;
    const int lane = tid & 31;
    const int w    = tid >> 5;
    const int bh   = blockIdx.y;
    const int t    = blockIdx.x * 16 + w;

    const float* q1p = g_q1 + ((size_t)bh * Tt + t) * HH;
    const float* q2p = g_q2 + ((size_t)bh * Tt + t) * HH;
    ((float4*)q1s[w])[lane] = ((const float4*)q1p)[lane];
    ((float4*)q2s[w])[lane] = ((const float4*)q2p)[lane];
    __syncwarp();

    float m1 = -1e30f, m2 = -1e30f, l1 = 0.f, l2 = 0.f;
    float acc1[8], acc2[8];
#pragma unroll
    for (int i = 0; i < 8; i++) { acc1[i] = 0.f; acc2[i] = 0.f; }

    const int ntiles = (blockIdx.x * 16 + 15) / 32 + 1;
    const float* k1b = g_k1 + (size_t)bh * Tt * HH;
    const float* k2b = g_k2 + (size_t)bh * Tt * HH;
    const float* vb  = g_vt + (size_t)bh * Tt * HD;

    const int row = tid >> 4;        // 0..31
    const int cg  = tid & 15;

    for (int kb = 0; kb < ntiles; kb++) {
        __syncthreads();
        {
            const float* s1 = k1b + (size_t)(kb * 32 + row) * HH + cg * 8;
            float4 x0 = ((const float4*)s1)[0];
            float4 x1 = ((const float4*)s1)[1];
            float* dp = &k1s[row][cg * 8];
            dp[0]=x0.x; dp[1]=x0.y; dp[2]=x0.z; dp[3]=x0.w;
            dp[4]=x1.x; dp[5]=x1.y; dp[6]=x1.z; dp[7]=x1.w;

            const float* s2 = k2b + (size_t)(kb * 32 + row) * HH + cg * 8;
            float4 y0 = ((const float4*)s2)[0];
            float4 y1 = ((const float4*)s2)[1];
            float* dq = &k2s[row][cg * 8];
            dq[0]=y0.x; dq[1]=y0.y; dq[2]=y0.z; dq[3]=y0.w;
            dq[4]=y1.x; dq[5]=y1.y; dq[6]=y1.z; dq[7]=y1.w;

            const float* sv = vb + (size_t)(kb * 32 + row) * HD + cg * 16;
            float4* dv = (float4*)&vsm[row][cg * 16];
            dv[0] = ((const float4*)sv)[0];
            dv[1] = ((const float4*)sv)[1];
            dv[2] = ((const float4*)sv)[2];
            dv[3] = ((const float4*)sv)[3];
        }
        __syncthreads();

        int krem = t - kb * 32 + 1;
        if (krem > 0) {
            int nk = krem < 32 ? krem : 32;
            float s1 = 0.f, s2 = 0.f;
            const float* kr1 = k1s[lane];
            const float* kr2 = k2s[lane];
            const float* qa  = q1s[w];
            const float* qb  = q2s[w];
#pragma unroll 16
            for (int d = 0; d < HH; d++) {
                s1 = fmaf(qa[d], kr1[d], s1);
                s2 = fmaf(qb[d], kr2[d], s2);
            }
            s1 *= SCALE; s2 *= SCALE;
            if (lane >= nk) { s1 = -1e30f; s2 = -1e30f; }

            float mx1 = s1, mx2 = s2;
#pragma unroll
            for (int o = 16; o; o >>= 1) {
                mx1 = fmaxf(mx1, __shfl_xor_sync(0xffffffffu, mx1, o));
                mx2 = fmaxf(mx2, __shfl_xor_sync(0xffffffffu, mx2, o));
            }
            float nm1 = fmaxf(m1, mx1), nm2 = fmaxf(m2, mx2);
            float p1 = __expf(s1 - nm1), p2 = __expf(s2 - nm2);
            float c1 = __expf(m1 - nm1), c2 = __expf(m2 - nm2);
            float sp1 = p1, sp2 = p2;
#pragma unroll
            for (int o = 16; o; o >>= 1) {
                sp1 += __shfl_xor_sync(0xffffffffu, sp1, o);
                sp2 += __shfl_xor_sync(0xffffffffu, sp2, o);
            }
            l1 = l1 * c1 + sp1; l2 = l2 * c2 + sp2;
            m1 = nm1; m2 = nm2;
#pragma unroll
            for (int i = 0; i < 8; i++) { acc1[i] *= c1; acc2[i] *= c2; }

#pragma unroll 4
            for (int jj = 0; jj < 32; jj++) {
                float pj1 = __shfl_sync(0xffffffffu, p1, jj);
                float pj2 = __shfl_sync(0xffffffffu, p2, jj);
                const float* vr = vsm[jj];
#pragma unroll
                for (int i = 0; i < 8; i++) {
                    float vv = vr[lane + 32 * i];
                    acc1[i] = fmaf(pj1, vv, acc1[i]);
                    acc2[i] = fmaf(pj2, vv, acc2[i]);
                }
            }
        }
    }

    float lam = g_lam;
    float r1 = 1.f / l1, r2 = lam / l2;
    int b = bh >> 3, h = bh & 7;
    float* yp = g_y + ((size_t)(b * Tt) + t) * Cc + h * HD;
#pragma unroll
    for (int i = 0; i < 8; i++)
        yp[lane + 32 * i] = acc1[i] * r1 - acc2[i] * r2;
}

// ---------------- launcher ----------------
extern "C" void kernel_launch(void* const* d_in, const int* in_sizes, int n_in,
                              void* d_out, int out_size)
{
    const float* x   = (const float*)d_in[0];
    const float* wq  = (const float*)d_in[1];
    const float* wk  = (const float*)d_in[2];
    const float* wv  = (const float*)d_in[3];
    const float* wo  = (const float*)d_in[4];
    const float* lq1 = (const float*)d_in[5];
    const float* lk1 = (const float*)d_in[6];
    const float* lq2 = (const float*)d_in[7];
    const float* lk2 = (const float*)d_in[8];
    float* out = (float*)d_out;

    void *pQ, *pK, *pV, *pY;
    cudaGetSymbolAddress(&pQ, g_Q);
    cudaGetSymbolAddress(&pK, g_K);
    cudaGetSymbolAddress(&pV, g_V);
    cudaGetSymbolAddress(&pY, g_y);

    dim3 gg(Cc / 128, (Bsz * Tt) / 128);
    sgemm_nt<<<gg, 256>>>(x, wq, (float*)pQ, Bsz * Tt, Cc, Cc, 1.0f);
    sgemm_nt<<<gg, 256>>>(x, wk, (float*)pK, Bsz * Tt, Cc, Cc, 1.0f);
    sgemm_nt<<<gg, 256>>>(x, wv, (float*)pV, Bsz * Tt, Cc, Cc, 1.0f);
    lam_kernel<<<1, 256>>>(lq1, lk1, lq2, lk2);
    prep_kernel<<<Bsz * Tt * NH, 128>>>();

    int smem = (2 * 32 * 129 + 32 * 256 + 2 * 16 * 128) * 4;  // 82176 B
    cudaFuncSetAttribute(attn_kernel, cudaFuncAttributeMaxDynamicSharedMemorySize, smem);
    attn_kernel<<<dim3(Tt / 16, Bsz * NH), 512, smem>>>();

    sgemm_nt<<<gg, 256>>>((const float*)pY, wo, out, Bsz * Tt, Cc, Cc, 0.8f);
}